// round 2
// baseline (speedup 1.0000x reference)
#include <cuda_runtime.h>
#include <cuda_bf16.h>

#define MAXN 50000
#define MAXE 800000
#define HDIM 64
#define SCAN_BLK 512

// ---------------- scratch (__device__ globals; no allocation allowed) -------
__device__ float g_hA [MAXN * HDIM];
__device__ float g_hB [MAXN * HDIM];
__device__ float g_pA [MAXN * HDIM];
__device__ float g_pB [MAXN * HDIM];
__device__ float g_EsA[MAXN * HDIM];
__device__ float g_EsB[MAXN * HDIM];
__device__ float g_S  [MAXN * HDIM];
__device__ float g_eraw[MAXN * 16];
__device__ float g_deg[MAXN];
__device__ int   g_degi[MAXN];
__device__ int   g_incl[MAXN];
__device__ int   g_bsum[256];
__device__ int   g_rowstart[MAXN + 1];
__device__ int   g_cursor[MAXN];
__device__ int   g_cols[MAXE];
__device__ float g_Wh [320 * HDIM];   // hm_W[l] @ HuB
__device__ float g_Vp [192 * HDIM];   // pm_W[l] @ PuB
__device__ float g_bmh[HDIM];
__device__ float g_bmp[HDIM];

// ---------------------------------------------------------------------------
__global__ void zero_f(float* p, int n) {
    int i = blockIdx.x * blockDim.x + threadIdx.x;
    if (i < n) p[i] = 0.0f;
}
__global__ void zero_i(int* p, int n) {
    int i = blockIdx.x * blockDim.x + threadIdx.x;
    if (i < n) p[i] = 0;
}
__global__ void hist_i(const int* __restrict__ rec, int* __restrict__ deg, int E) {
    int i = blockIdx.x * blockDim.x + threadIdx.x;
    if (i < E) atomicAdd(&deg[rec[i]], 1);
}
__global__ void copy_i(const int* s, int* d, int n) {
    int i = blockIdx.x * blockDim.x + threadIdx.x;
    if (i < n) d[i] = s[i];
}

// 3-phase exclusive scan of degrees -> row_start, plus float degree
__global__ void scan1(const int* __restrict__ deg, int* __restrict__ incl,
                      int* __restrict__ bsum, int n) {
    __shared__ int sh[SCAN_BLK];
    int base = blockIdx.x * SCAN_BLK;
    int t = threadIdx.x;
    int v = (base + t < n) ? deg[base + t] : 0;
    sh[t] = v;
    __syncthreads();
    for (int off = 1; off < SCAN_BLK; off <<= 1) {
        int x = (t >= off) ? sh[t - off] : 0;
        __syncthreads();
        sh[t] += x;
        __syncthreads();
    }
    if (base + t < n) incl[base + t] = sh[t];
    if (t == SCAN_BLK - 1) bsum[blockIdx.x] = sh[t];
}
__global__ void scan2(int* bsum, int nb) {
    if (blockIdx.x == 0 && threadIdx.x == 0) {
        int acc = 0;
        for (int i = 0; i < nb; i++) { int v = bsum[i]; bsum[i] = acc; acc += v; }
    }
}
__global__ void scan3(const int* __restrict__ deg, const int* __restrict__ incl,
                      const int* __restrict__ bsum, int* __restrict__ row_start,
                      float* __restrict__ degf, int n, int E) {
    int i = blockIdx.x * blockDim.x + threadIdx.x;
    if (i < n) {
        int inc = incl[i] + bsum[i / SCAN_BLK];
        row_start[i] = inc - deg[i];
        degf[i] = (float)deg[i];
        if (i == n - 1) row_start[n] = E;
    }
}
__global__ void csr_fill(const int* __restrict__ send, const int* __restrict__ rec,
                         int* __restrict__ cursor, int* __restrict__ cols, int E) {
    int e = blockIdx.x * blockDim.x + threadIdx.x;
    if (e < E) {
        int pos = atomicAdd(&cursor[rec[e]], 1);
        cols[pos] = send[e];
    }
}

// segment-sum raw edge features [E,16] -> [N,16] (runs once; atomics OK)
__global__ void e_scatter(const float* __restrict__ e, const int* __restrict__ rec,
                          float* __restrict__ out, int E) {
    int i = blockIdx.x * blockDim.x + threadIdx.x;
    if (i < E * 4) {
        int edge = i >> 2;
        int f4 = (i & 3) * 4;
        int r = rec[edge];
        float4 v = *(const float4*)(e + (size_t)edge * 16 + f4);
        float* d = out + (size_t)r * 16 + f4;
        atomicAdd(d + 0, v.x);
        atomicAdd(d + 1, v.y);
        atomicAdd(d + 2, v.z);
        atomicAdd(d + 3, v.w);
    }
}

// ---------------------------------------------------------------------------
#define FMA16(x, w0, w1, w2, w3, a)                         \
    a[0]  = fmaf(x, w0.x, a[0]);  a[1]  = fmaf(x, w0.y, a[1]);  \
    a[2]  = fmaf(x, w0.z, a[2]);  a[3]  = fmaf(x, w0.w, a[3]);  \
    a[4]  = fmaf(x, w1.x, a[4]);  a[5]  = fmaf(x, w1.y, a[5]);  \
    a[6]  = fmaf(x, w1.z, a[6]);  a[7]  = fmaf(x, w1.w, a[7]);  \
    a[8]  = fmaf(x, w2.x, a[8]);  a[9]  = fmaf(x, w2.y, a[9]);  \
    a[10] = fmaf(x, w2.z, a[10]); a[11] = fmaf(x, w2.w, a[11]); \
    a[12] = fmaf(x, w3.x, a[12]); a[13] = fmaf(x, w3.y, a[13]); \
    a[14] = fmaf(x, w3.z, a[14]); a[15] = fmaf(x, w3.w, a[15]);

// K=64 MAC: acc[r][:] += X[rowc[r], :] @ swW  (columns cg*16..cg*16+15)
__device__ __forceinline__ void mac64(const float* __restrict__ X,
                                      const float* __restrict__ swW,
                                      const int rowc[4], int cg, float acc[4][16]) {
#pragma unroll 1
    for (int k4 = 0; k4 < 64; k4 += 4) {
        float4 xv[4];
#pragma unroll
        for (int r = 0; r < 4; r++)
            xv[r] = *(const float4*)(X + (size_t)rowc[r] * 64 + k4);
#pragma unroll
        for (int kk = 0; kk < 4; kk++) {
            const float4* wrow = (const float4*)&swW[(k4 + kk) * 64 + cg * 16];
            float4 w0 = wrow[0], w1 = wrow[1], w2 = wrow[2], w3 = wrow[3];
#pragma unroll
            for (int r = 0; r < 4; r++) {
                float x = (kk == 0) ? xv[r].x : (kk == 1) ? xv[r].y
                          : (kk == 2) ? xv[r].z : xv[r].w;
                FMA16(x, w0, w1, w2, w3, acc[r]);
            }
        }
    }
}

// Fully fused node op (all K=64 operands):
//   C = deg .* (S1@Ws1 + S2@Ws2 + sb) + U1@Wu1 + U2@Wu2 + ub + CSR-gather(G)
// any operand pointer may be null.
__global__ __launch_bounds__(256) void node_fused(
    const float* __restrict__ S1, const float* __restrict__ Ws1,
    const float* __restrict__ S2, const float* __restrict__ Ws2,
    const float* __restrict__ sb, const float* __restrict__ degf,
    const float* __restrict__ U1x, const float* __restrict__ Wu1,
    const float* __restrict__ U2x, const float* __restrict__ Wu2,
    const float* __restrict__ ub,
    const float* __restrict__ G, const int* __restrict__ row_start,
    const int* __restrict__ csr_cols,
    float* __restrict__ C, int N)
{
    extern __shared__ float sw[];  // up to 4 x 64x64 weight tiles

    {   // cooperative weight staging
        if (Ws1) for (int i = threadIdx.x * 4; i < 4096; i += 1024)
            *(float4*)&sw[i] = *(const float4*)&Ws1[i];
        if (Ws2) for (int i = threadIdx.x * 4; i < 4096; i += 1024)
            *(float4*)&sw[4096 + i] = *(const float4*)&Ws2[i];
        if (Wu1) for (int i = threadIdx.x * 4; i < 4096; i += 1024)
            *(float4*)&sw[8192 + i] = *(const float4*)&Wu1[i];
        if (Wu2) for (int i = threadIdx.x * 4; i < 4096; i += 1024)
            *(float4*)&sw[12288 + i] = *(const float4*)&Wu2[i];
    }
    __syncthreads();

    const int cg = threadIdx.x & 3;
    const int rl = threadIdx.x >> 2;
    const int row0 = blockIdx.x * 256 + rl * 4;

    float acc[4][16];
#pragma unroll
    for (int r = 0; r < 4; r++)
#pragma unroll
        for (int j = 0; j < 16; j++) acc[r][j] = 0.0f;

    int rowc[4];
#pragma unroll
    for (int r = 0; r < 4; r++) {
        int rr = row0 + r;
        rowc[r] = rr < N ? rr : (N - 1);
    }

    // scaled part
    if (S1) mac64(S1, sw, rowc, cg, acc);
    if (S2) mac64(S2, sw + 4096, rowc, cg, acc);
    if (sb) {
        float4 b0 = *(const float4*)&sb[cg * 16 + 0];
        float4 b1 = *(const float4*)&sb[cg * 16 + 4];
        float4 b2 = *(const float4*)&sb[cg * 16 + 8];
        float4 b3 = *(const float4*)&sb[cg * 16 + 12];
#pragma unroll
        for (int r = 0; r < 4; r++) {
            acc[r][0] += b0.x;  acc[r][1] += b0.y;  acc[r][2] += b0.z;  acc[r][3] += b0.w;
            acc[r][4] += b1.x;  acc[r][5] += b1.y;  acc[r][6] += b1.z;  acc[r][7] += b1.w;
            acc[r][8] += b2.x;  acc[r][9] += b2.y;  acc[r][10] += b2.z; acc[r][11] += b2.w;
            acc[r][12] += b3.x; acc[r][13] += b3.y; acc[r][14] += b3.z; acc[r][15] += b3.w;
        }
    }
    if (degf) {
#pragma unroll
        for (int r = 0; r < 4; r++) {
            float dg = degf[rowc[r]];
#pragma unroll
            for (int j = 0; j < 16; j++) acc[r][j] *= dg;
        }
    }

    // unscaled part
    if (U1x) mac64(U1x, sw + 8192, rowc, cg, acc);
    if (U2x) mac64(U2x, sw + 12288, rowc, cg, acc);
    if (ub) {
        float4 b0 = *(const float4*)&ub[cg * 16 + 0];
        float4 b1 = *(const float4*)&ub[cg * 16 + 4];
        float4 b2 = *(const float4*)&ub[cg * 16 + 8];
        float4 b3 = *(const float4*)&ub[cg * 16 + 12];
#pragma unroll
        for (int r = 0; r < 4; r++) {
            acc[r][0] += b0.x;  acc[r][1] += b0.y;  acc[r][2] += b0.z;  acc[r][3] += b0.w;
            acc[r][4] += b1.x;  acc[r][5] += b1.y;  acc[r][6] += b1.z;  acc[r][7] += b1.w;
            acc[r][8] += b2.x;  acc[r][9] += b2.y;  acc[r][10] += b2.z; acc[r][11] += b2.w;
            acc[r][12] += b3.x; acc[r][13] += b3.y; acc[r][14] += b3.z; acc[r][15] += b3.w;
        }
    }

    // CSR gather-sum: acc[r] += sum over in-edges of G[col]
    if (G) {
#pragma unroll 1
        for (int r = 0; r < 4; r++) {
            int row = row0 + r;
            if (row >= N) continue;
            int js = row_start[row];
            int je = row_start[row + 1];
#pragma unroll 1
            for (int j = js; j < je; j++) {
                int c = csr_cols[j];
                const float4* gp = (const float4*)(G + (size_t)c * 64 + cg * 16);
                float4 a = gp[0], b = gp[1], d = gp[2], w = gp[3];
                acc[r][0] += a.x;  acc[r][1] += a.y;  acc[r][2] += a.z;  acc[r][3] += a.w;
                acc[r][4] += b.x;  acc[r][5] += b.y;  acc[r][6] += b.z;  acc[r][7] += b.w;
                acc[r][8] += d.x;  acc[r][9] += d.y;  acc[r][10] += d.z; acc[r][11] += d.w;
                acc[r][12] += w.x; acc[r][13] += w.y; acc[r][14] += w.z; acc[r][15] += w.w;
            }
        }
    }

#pragma unroll
    for (int r = 0; r < 4; r++) {
        int row = row0 + r;
        if (row < N) {
            float* cp = C + (size_t)row * 64 + cg * 16;
            *(float4*)(cp + 0)  = make_float4(acc[r][0],  acc[r][1],  acc[r][2],  acc[r][3]);
            *(float4*)(cp + 4)  = make_float4(acc[r][4],  acc[r][5],  acc[r][6],  acc[r][7]);
            *(float4*)(cp + 8)  = make_float4(acc[r][8],  acc[r][9],  acc[r][10], acc[r][11]);
            *(float4*)(cp + 12) = make_float4(acc[r][12], acc[r][13], acc[r][14], acc[r][15]);
        }
    }
}

// ---------------------------------------------------------------------------
// General-K fused GEMM (embeddings + weight composites), same as R1
__global__ __launch_bounds__(256) void gemm_fused(
    const float* __restrict__ A, const float* __restrict__ Wa, int Ka,
    const float* __restrict__ B, const float* __restrict__ Wb, int Kb,
    const float* __restrict__ bias1, const float* __restrict__ degf,
    const float* __restrict__ D, const float* __restrict__ Wd, int Kd,
    float* __restrict__ C, int N)
{
    extern __shared__ float sw[];
    {
        int nA = Ka * 64, nB = Kb * 64, nD = Kd * 64;
        for (int i = threadIdx.x * 4; i < nA; i += blockDim.x * 4)
            *(float4*)&sw[i] = *(const float4*)&Wa[i];
        for (int i = threadIdx.x * 4; i < nB; i += blockDim.x * 4)
            *(float4*)&sw[nA + i] = *(const float4*)&Wb[i];
        for (int i = threadIdx.x * 4; i < nD; i += blockDim.x * 4)
            *(float4*)&sw[nA + nB + i] = *(const float4*)&Wd[i];
    }
    __syncthreads();

    const int cg = threadIdx.x & 3;
    const int rl = threadIdx.x >> 2;
    const int row0 = blockIdx.x * 256 + rl * 4;

    float acc[4][16];
#pragma unroll
    for (int r = 0; r < 4; r++)
#pragma unroll
        for (int j = 0; j < 16; j++) acc[r][j] = 0.0f;

    int rowc[4];
#pragma unroll
    for (int r = 0; r < 4; r++) {
        int rr = row0 + r;
        rowc[r] = rr < N ? rr : (N - 1);
    }

#pragma unroll 1
    for (int m = 0; m < 2; m++) {
        const float* X = (m == 0) ? A : B;
        int K = (m == 0) ? Ka : Kb;
        int off = (m == 0) ? 0 : Ka;
        if (X == nullptr || K == 0) continue;
#pragma unroll 1
        for (int k4 = 0; k4 < K; k4 += 4) {
            float4 xv[4];
#pragma unroll
            for (int r = 0; r < 4; r++)
                xv[r] = *(const float4*)(X + (size_t)rowc[r] * K + k4);
#pragma unroll
            for (int kk = 0; kk < 4; kk++) {
                const float4* wrow = (const float4*)&sw[(off + k4 + kk) * 64 + cg * 16];
                float4 w0 = wrow[0], w1 = wrow[1], w2 = wrow[2], w3 = wrow[3];
#pragma unroll
                for (int r = 0; r < 4; r++) {
                    float x = (kk == 0) ? xv[r].x : (kk == 1) ? xv[r].y
                              : (kk == 2) ? xv[r].z : xv[r].w;
                    FMA16(x, w0, w1, w2, w3, acc[r]);
                }
            }
        }
    }

    if (bias1) {
        float4 b0 = *(const float4*)&bias1[cg * 16 + 0];
        float4 b1 = *(const float4*)&bias1[cg * 16 + 4];
        float4 b2 = *(const float4*)&bias1[cg * 16 + 8];
        float4 b3 = *(const float4*)&bias1[cg * 16 + 12];
#pragma unroll
        for (int r = 0; r < 4; r++) {
            acc[r][0] += b0.x;  acc[r][1] += b0.y;  acc[r][2] += b0.z;  acc[r][3] += b0.w;
            acc[r][4] += b1.x;  acc[r][5] += b1.y;  acc[r][6] += b1.z;  acc[r][7] += b1.w;
            acc[r][8] += b2.x;  acc[r][9] += b2.y;  acc[r][10] += b2.z; acc[r][11] += b2.w;
            acc[r][12] += b3.x; acc[r][13] += b3.y; acc[r][14] += b3.z; acc[r][15] += b3.w;
        }
    }
    if (degf) {
#pragma unroll
        for (int r = 0; r < 4; r++) {
            float dg = degf[rowc[r]];
#pragma unroll
            for (int j = 0; j < 16; j++) acc[r][j] *= dg;
        }
    }
    if (D != nullptr && Kd > 0) {
        int off = Ka + Kb;
#pragma unroll 1
        for (int k4 = 0; k4 < Kd; k4 += 4) {
            float4 xv[4];
#pragma unroll
            for (int r = 0; r < 4; r++)
                xv[r] = *(const float4*)(D + (size_t)rowc[r] * Kd + k4);
#pragma unroll
            for (int kk = 0; kk < 4; kk++) {
                const float4* wrow = (const float4*)&sw[(off + k4 + kk) * 64 + cg * 16];
                float4 w0 = wrow[0], w1 = wrow[1], w2 = wrow[2], w3 = wrow[3];
#pragma unroll
                for (int r = 0; r < 4; r++) {
                    float x = (kk == 0) ? xv[r].x : (kk == 1) ? xv[r].y
                              : (kk == 2) ? xv[r].z : xv[r].w;
                    FMA16(x, w0, w1, w2, w3, acc[r]);
                }
            }
        }
    }

#pragma unroll
    for (int r = 0; r < 4; r++) {
        int row = row0 + r;
        if (row < N) {
            float* cp = C + (size_t)row * 64 + cg * 16;
            *(float4*)(cp + 0)  = make_float4(acc[r][0],  acc[r][1],  acc[r][2],  acc[r][3]);
            *(float4*)(cp + 4)  = make_float4(acc[r][4],  acc[r][5],  acc[r][6],  acc[r][7]);
            *(float4*)(cp + 8)  = make_float4(acc[r][8],  acc[r][9],  acc[r][10], acc[r][11]);
            *(float4*)(cp + 12) = make_float4(acc[r][12], acc[r][13], acc[r][14], acc[r][15]);
        }
    }
}

// ---------------------------------------------------------------------------
extern "C" void kernel_launch(void* const* d_in, const int* in_sizes, int n_in,
                              void* d_out, int out_size) {
    const float* h_in = (const float*)d_in[0];
    const float* e_in = (const float*)d_in[1];
    const float* p_in = (const float*)d_in[2];
    const int*   eidx = (const int*)d_in[3];
    const float* he_W = (const float*)d_in[4];
    const float* he_b = (const float*)d_in[5];
    const float* ee_W = (const float*)d_in[6];
    const float* ee_b = (const float*)d_in[7];
    const float* pe_W = (const float*)d_in[8];
    const float* pe_b = (const float*)d_in[9];
    const float* hm_W = (const float*)d_in[10];
    const float* hm_b = (const float*)d_in[11];
    const float* hu_W = (const float*)d_in[12];
    const float* hu_b = (const float*)d_in[13];
    const float* eu_W = (const float*)d_in[14];
    const float* eu_b = (const float*)d_in[15];
    const float* pm_W = (const float*)d_in[16];
    const float* pm_b = (const float*)d_in[17];
    const float* pu_W = (const float*)d_in[18];
    const float* pu_b = (const float*)d_in[19];

    const int N = in_sizes[0] / 128;
    const int E = in_sizes[3] / 2;
    const int* send = eidx;
    const int* rec  = eidx + E;
    float* out = (float*)d_out;

    static bool attr_set = false;
    if (!attr_set) {
        cudaFuncSetAttribute(node_fused, cudaFuncAttributeMaxDynamicSharedMemorySize, 65536);
        attr_set = true;
    }

    float *hA, *hB, *pA, *pB, *EsA, *EsB, *S, *eraw, *deg, *Wh, *Vp, *bmh, *bmp;
    int *degi, *incl, *bsum, *rowstart, *cursor, *cols;
    cudaGetSymbolAddress((void**)&hA,  g_hA);
    cudaGetSymbolAddress((void**)&hB,  g_hB);
    cudaGetSymbolAddress((void**)&pA,  g_pA);
    cudaGetSymbolAddress((void**)&pB,  g_pB);
    cudaGetSymbolAddress((void**)&EsA, g_EsA);
    cudaGetSymbolAddress((void**)&EsB, g_EsB);
    cudaGetSymbolAddress((void**)&S,   g_S);
    cudaGetSymbolAddress((void**)&eraw, g_eraw);
    cudaGetSymbolAddress((void**)&deg, g_deg);
    cudaGetSymbolAddress((void**)&degi, g_degi);
    cudaGetSymbolAddress((void**)&incl, g_incl);
    cudaGetSymbolAddress((void**)&bsum, g_bsum);
    cudaGetSymbolAddress((void**)&rowstart, g_rowstart);
    cudaGetSymbolAddress((void**)&cursor, g_cursor);
    cudaGetSymbolAddress((void**)&cols, g_cols);
    cudaGetSymbolAddress((void**)&Wh,  g_Wh);
    cudaGetSymbolAddress((void**)&Vp,  g_Vp);
    cudaGetSymbolAddress((void**)&bmh, g_bmh);
    cudaGetSymbolAddress((void**)&bmp, g_bmp);

    const int GB = (N + 255) / 256;
    const int NB_SCAN = (N + SCAN_BLK - 1) / SCAN_BLK;

    // ---- CSR build + raw edge segment-sum ----
    zero_i<<<(N + 255) / 256, 256>>>(degi, N);
    zero_f<<<(N * 16 + 255) / 256, 256>>>(eraw, N * 16);
    hist_i<<<(E + 255) / 256, 256>>>(rec, degi, E);
    scan1<<<NB_SCAN, SCAN_BLK>>>(degi, incl, bsum, N);
    scan2<<<1, 32>>>(bsum, NB_SCAN);
    scan3<<<(N + 255) / 256, 256>>>(degi, incl, bsum, rowstart, deg, N, E);
    copy_i<<<(N + 255) / 256, 256>>>(rowstart, cursor, N);
    csr_fill<<<(E + 255) / 256, 256>>>(send, rec, cursor, cols, E);
    e_scatter<<<(E * 4 + 255) / 256, 256>>>(e_in, rec, eraw, E);

    // ---- embeddings ----
    gemm_fused<<<GB, 256, 128 * 64 * 4>>>(h_in, he_W, 128, nullptr, nullptr, 0,
                                          he_b, nullptr, nullptr, nullptr, 0, hA, N);
    gemm_fused<<<GB, 256, 16 * 64 * 4>>>(p_in, pe_W, 16, nullptr, nullptr, 0,
                                         pe_b, nullptr, nullptr, nullptr, 0, pA, N);
    gemm_fused<<<GB, 256, 16 * 64 * 4>>>(nullptr, nullptr, 0, nullptr, nullptr, 0,
                                         ee_b, deg, eraw, ee_W, 16, EsA, N);

    for (int l = 0; l < 4; l++) {
        const float* hmW_l = hm_W + (size_t)l * 320 * 64;
        const float* bhm   = hm_b + (size_t)l * 64;
        const float* HuA   = hu_W + (size_t)l * 128 * 64;
        const float* HuB   = HuA + 64 * 64;
        const float* bhu   = hu_b + (size_t)l * 64;
        const float* U1    = eu_W + (size_t)l * 192 * 64;
        const float* U2    = U1 + 64 * 64;
        const float* U3    = U1 + 128 * 64;
        const float* beu   = eu_b + (size_t)l * 64;
        const float* pmW_l = pm_W + (size_t)l * 192 * 64;
        const float* bpm   = pm_b + (size_t)l * 64;
        const float* PuA   = pu_W + (size_t)l * 128 * 64;
        const float* PuB   = PuA + 64 * 64;
        const float* bpu   = pu_b + (size_t)l * 64;

        const bool last = (l == 3);
        float* hOut = last ? out : hB;
        float* pOut = last ? (out + (size_t)N * 64) : pB;

        // weight composites: Wh = hm_W[l]@HuB (320x64), bmh = bhm@HuB,
        //                    Vp = pm_W[l]@PuB (192x64), bmp = bpm@PuB
        gemm_fused<<<2, 256, 64 * 64 * 4>>>(hmW_l, HuB, 64, nullptr, nullptr, 0,
                                            nullptr, nullptr, nullptr, nullptr, 0, Wh, 320);
        gemm_fused<<<1, 256, 64 * 64 * 4>>>(bhm, HuB, 64, nullptr, nullptr, 0,
                                            nullptr, nullptr, nullptr, nullptr, 0, bmh, 1);
        gemm_fused<<<1, 256, 64 * 64 * 4>>>(pmW_l, PuB, 64, nullptr, nullptr, 0,
                                            nullptr, nullptr, nullptr, nullptr, 0, Vp, 192);
        gemm_fused<<<1, 256, 64 * 64 * 4>>>(bpm, PuB, 64, nullptr, nullptr, 0,
                                            nullptr, nullptr, nullptr, nullptr, 0, bmp, 1);

        const float* W1h = Wh;                 // W_hsend @ HuB
        const float* W2h = Wh + 4096;          // W_psend @ HuB
        const float* W3h = Wh + 2 * 4096;      // W_hrec  @ HuB
        const float* W4h = Wh + 3 * 4096;      // W_prec  @ HuB
        const float* W5h = Wh + 4 * 4096;      // W_e     @ HuB
        const float* V1p = Vp;                 // V_send @ PuB
        const float* V2p = Vp + 4096;          // V_rec  @ PuB
        const float* V3p = Vp + 2 * 4096;      // V_e    @ PuB

        // S = h@W1h + p@W2h
        node_fused<<<GB, 256, 65536>>>(nullptr, nullptr, nullptr, nullptr,
                                       nullptr, nullptr,
                                       hA, W1h, pA, W2h, nullptr,
                                       nullptr, nullptr, nullptr, S, N);
        // h' = deg.*(h@W3h + p@W4h + bmh) + h@HuA + Esum@W5h + bhu + gather(S)
        node_fused<<<GB, 256, 65536>>>(hA, W3h, pA, W4h, bmh, deg,
                                       hA, HuA, EsA, W5h, bhu,
                                       S, rowstart, cols, hOut, N);
        // T1 = h'@U1
        node_fused<<<GB, 256, 65536>>>(nullptr, nullptr, nullptr, nullptr,
                                       nullptr, nullptr,
                                       hOut, U1, nullptr, nullptr, nullptr,
                                       nullptr, nullptr, nullptr, S, N);
        // Esum' = deg.*(h'@U2 + beu) + Esum@U3 + gather(T1)
        node_fused<<<GB, 256, 65536>>>(hOut, U2, nullptr, nullptr, beu, deg,
                                       EsA, U3, nullptr, nullptr, nullptr,
                                       S, rowstart, cols, EsB, N);
        // P1 = p@V1p
        node_fused<<<GB, 256, 65536>>>(nullptr, nullptr, nullptr, nullptr,
                                       nullptr, nullptr,
                                       pA, V1p, nullptr, nullptr, nullptr,
                                       nullptr, nullptr, nullptr, S, N);
        // p' = deg.*(p@V2p + bmp) + p@PuA + Esum'@V3p + bpu + gather(P1)
        node_fused<<<GB, 256, 65536>>>(pA, V2p, nullptr, nullptr, bmp, deg,
                                       pA, PuA, EsB, V3p, bpu,
                                       S, rowstart, cols, pOut, N);

        float* t;
        t = hA; hA = hOut; hB = t;
        t = pA; pA = pOut; pB = t;
        t = EsA; EsA = EsB; EsB = t;
    }
}

// round 5
// speedup vs baseline: 1.1771x; 1.1771x over previous
#include <cuda_runtime.h>
#include <cuda_bf16.h>

#define MAXN 50000
#define MAXE 800000
#define HDIM 64
#define SCAN_BLK 512

// ---------------- scratch (__device__ globals) ------------------------------
__device__ float g_hA [MAXN * HDIM];
__device__ float g_hB [MAXN * HDIM];
__device__ float g_pA [MAXN * HDIM];
__device__ float g_pB [MAXN * HDIM];
__device__ float g_EsA[MAXN * HDIM];
__device__ float g_EsB[MAXN * HDIM];
__device__ float g_S  [MAXN * HDIM];
__device__ float g_eraw[MAXN * 16];
__device__ float g_deg[MAXN];
__device__ int   g_degi[MAXN];
__device__ int   g_incl[MAXN];
__device__ int   g_bsum[256];
__device__ int   g_rowstart[MAXN + 1];
__device__ int   g_cursor[MAXN];
__device__ int   g_cols[MAXE];
__device__ float g_Wh [320 * HDIM];   // hm_W[l] @ HuB
__device__ float g_Vp [192 * HDIM];   // pm_W[l] @ PuB
__device__ float g_bmh[HDIM];
__device__ float g_bmp[HDIM];

// ---------------------------------------------------------------------------
__global__ void zero_f(float* p, int n) {
    int i = blockIdx.x * blockDim.x + threadIdx.x;
    if (i < n) p[i] = 0.0f;
}
__global__ void zero_i(int* p, int n) {
    int i = blockIdx.x * blockDim.x + threadIdx.x;
    if (i < n) p[i] = 0;
}
__global__ void hist_i(const int* __restrict__ rec, int* __restrict__ deg, int E) {
    int i = blockIdx.x * blockDim.x + threadIdx.x;
    if (i < E) atomicAdd(&deg[rec[i]], 1);
}
__global__ void copy_i(const int* s, int* d, int n) {
    int i = blockIdx.x * blockDim.x + threadIdx.x;
    if (i < n) d[i] = s[i];
}
__global__ void scan1(const int* __restrict__ deg, int* __restrict__ incl,
                      int* __restrict__ bsum, int n) {
    __shared__ int sh[SCAN_BLK];
    int base = blockIdx.x * SCAN_BLK;
    int t = threadIdx.x;
    int v = (base + t < n) ? deg[base + t] : 0;
    sh[t] = v;
    __syncthreads();
    for (int off = 1; off < SCAN_BLK; off <<= 1) {
        int x = (t >= off) ? sh[t - off] : 0;
        __syncthreads();
        sh[t] += x;
        __syncthreads();
    }
    if (base + t < n) incl[base + t] = sh[t];
    if (t == SCAN_BLK - 1) bsum[blockIdx.x] = sh[t];
}
__global__ void scan2(int* bsum, int nb) {
    if (blockIdx.x == 0 && threadIdx.x == 0) {
        int acc = 0;
        for (int i = 0; i < nb; i++) { int v = bsum[i]; bsum[i] = acc; acc += v; }
    }
}
__global__ void scan3(const int* __restrict__ deg, const int* __restrict__ incl,
                      const int* __restrict__ bsum, int* __restrict__ row_start,
                      float* __restrict__ degf, int n, int E) {
    int i = blockIdx.x * blockDim.x + threadIdx.x;
    if (i < n) {
        int inc = incl[i] + bsum[i / SCAN_BLK];
        row_start[i] = inc - deg[i];
        degf[i] = (float)deg[i];
        if (i == n - 1) row_start[n] = E;
    }
}
__global__ void csr_fill(const int* __restrict__ send, const int* __restrict__ rec,
                         int* __restrict__ cursor, int* __restrict__ cols, int E) {
    int e = blockIdx.x * blockDim.x + threadIdx.x;
    if (e < E) {
        int pos = atomicAdd(&cursor[rec[e]], 1);
        cols[pos] = send[e];
    }
}

// segment-sum raw edge features [E,16] -> [N,16] (scalar atomics; runs once)
__global__ void e_scatter(const float* __restrict__ e, const int* __restrict__ rec,
                          float* __restrict__ out, int E) {
    int i = blockIdx.x * blockDim.x + threadIdx.x;
    if (i < E * 4) {
        int edge = i >> 2;
        int f4 = (i & 3) * 4;
        int r = __ldg(&rec[edge]);
        float4 v = *(const float4*)(e + (size_t)edge * 16 + f4);
        float* d = out + (size_t)r * 16 + f4;
        atomicAdd(d + 0, v.x);
        atomicAdd(d + 1, v.y);
        atomicAdd(d + 2, v.z);
        atomicAdd(d + 3, v.w);
    }
}

// dst[n,:] += sum_{j in CSR row n} G[cols[j],:]  — warp per node, no atomics
__global__ __launch_bounds__(256) void gather_add(
    const float* __restrict__ G, float* __restrict__ dst,
    const int* __restrict__ row_start, const int* __restrict__ cols, int N)
{
    int w = (blockIdx.x * blockDim.x + threadIdx.x) >> 5;
    int lane = threadIdx.x & 31;
    int nw = (gridDim.x * blockDim.x) >> 5;
    for (int n = w; n < N; n += nw) {
        int js = row_start[n], je = row_start[n + 1];
        float ax = 0.0f, ay = 0.0f;
        int j = js;
        for (; j + 4 <= je; j += 4) {
            int c0 = __ldg(&cols[j]);
            int c1 = __ldg(&cols[j + 1]);
            int c2 = __ldg(&cols[j + 2]);
            int c3 = __ldg(&cols[j + 3]);
            float2 v0 = *(const float2*)(G + (size_t)c0 * 64 + lane * 2);
            float2 v1 = *(const float2*)(G + (size_t)c1 * 64 + lane * 2);
            float2 v2 = *(const float2*)(G + (size_t)c2 * 64 + lane * 2);
            float2 v3 = *(const float2*)(G + (size_t)c3 * 64 + lane * 2);
            ax += (v0.x + v1.x) + (v2.x + v3.x);
            ay += (v0.y + v1.y) + (v2.y + v3.y);
        }
        for (; j < je; j++) {
            int c = __ldg(&cols[j]);
            float2 v = *(const float2*)(G + (size_t)c * 64 + lane * 2);
            ax += v.x; ay += v.y;
        }
        float2* d = (float2*)(dst + (size_t)n * 64 + lane * 2);
        float2 cur = *d;
        cur.x += ax; cur.y += ay;
        *d = cur;
    }
}

// ---------------------------------------------------------------------------
#define FMA16(x, w0, w1, w2, w3, a)                             \
    a[0]  = fmaf(x, w0.x, a[0]);  a[1]  = fmaf(x, w0.y, a[1]);  \
    a[2]  = fmaf(x, w0.z, a[2]);  a[3]  = fmaf(x, w0.w, a[3]);  \
    a[4]  = fmaf(x, w1.x, a[4]);  a[5]  = fmaf(x, w1.y, a[5]);  \
    a[6]  = fmaf(x, w1.z, a[6]);  a[7]  = fmaf(x, w1.w, a[7]);  \
    a[8]  = fmaf(x, w2.x, a[8]);  a[9]  = fmaf(x, w2.y, a[9]);  \
    a[10] = fmaf(x, w2.z, a[10]); a[11] = fmaf(x, w2.w, a[11]); \
    a[12] = fmaf(x, w3.x, a[12]); a[13] = fmaf(x, w3.y, a[13]); \
    a[14] = fmaf(x, w3.z, a[14]); a[15] = fmaf(x, w3.w, a[15]);

__device__ __forceinline__ void macK(const float* __restrict__ X, int K,
                                     const float* __restrict__ swW,
                                     const int rowc[4], int cg, float acc[4][16]) {
#pragma unroll 1
    for (int k4 = 0; k4 < K; k4 += 4) {
        float4 xv[4];
#pragma unroll
        for (int r = 0; r < 4; r++)
            xv[r] = *(const float4*)(X + (size_t)rowc[r] * K + k4);
#pragma unroll
        for (int kk = 0; kk < 4; kk++) {
            const float4* wrow = (const float4*)&swW[(k4 + kk) * 64 + cg * 16];
            float4 w0 = wrow[0], w1 = wrow[1], w2 = wrow[2], w3 = wrow[3];
#pragma unroll
            for (int r = 0; r < 4; r++) {
                float x = (kk == 0) ? xv[r].x : (kk == 1) ? xv[r].y
                          : (kk == 2) ? xv[r].z : xv[r].w;
                FMA16(x, w0, w1, w2, w3, acc[r]);
            }
        }
    }
}

__device__ __forceinline__ void addbias(const float* __restrict__ b, int cg,
                                        float acc[4][16]) {
    float4 b0 = *(const float4*)&b[cg * 16 + 0];
    float4 b1 = *(const float4*)&b[cg * 16 + 4];
    float4 b2 = *(const float4*)&b[cg * 16 + 8];
    float4 b3 = *(const float4*)&b[cg * 16 + 12];
#pragma unroll
    for (int r = 0; r < 4; r++) {
        acc[r][0] += b0.x;  acc[r][1] += b0.y;  acc[r][2] += b0.z;  acc[r][3] += b0.w;
        acc[r][4] += b1.x;  acc[r][5] += b1.y;  acc[r][6] += b1.z;  acc[r][7] += b1.w;
        acc[r][8] += b2.x;  acc[r][9] += b2.y;  acc[r][10] += b2.z; acc[r][11] += b2.w;
        acc[r][12] += b3.x; acc[r][13] += b3.y; acc[r][14] += b3.z; acc[r][15] += b3.w;
    }
}

// C = deg .* (A@Wa + B@Wb + b1) + D@Wd + E2@We + b2   (any operand nullable)
__global__ __launch_bounds__(256) void gemm_fused(
    const float* __restrict__ A, const float* __restrict__ Wa, int Ka,
    const float* __restrict__ B, const float* __restrict__ Wb, int Kb,
    const float* __restrict__ b1, const float* __restrict__ degf,
    const float* __restrict__ D, const float* __restrict__ Wd, int Kd,
    const float* __restrict__ E2, const float* __restrict__ We, int Ke,
    const float* __restrict__ b2,
    float* __restrict__ C, int N)
{
    extern __shared__ float sw[];
    const int offB = Ka * 64, offD = offB + Kb * 64, offE = offD + Kd * 64;
    {
        if (A)  for (int i = threadIdx.x * 4; i < Ka * 64; i += 1024)
            *(float4*)&sw[i] = *(const float4*)&Wa[i];
        if (B)  for (int i = threadIdx.x * 4; i < Kb * 64; i += 1024)
            *(float4*)&sw[offB + i] = *(const float4*)&Wb[i];
        if (D)  for (int i = threadIdx.x * 4; i < Kd * 64; i += 1024)
            *(float4*)&sw[offD + i] = *(const float4*)&Wd[i];
        if (E2) for (int i = threadIdx.x * 4; i < Ke * 64; i += 1024)
            *(float4*)&sw[offE + i] = *(const float4*)&We[i];
    }
    __syncthreads();

    const int cg = threadIdx.x & 3;
    const int rl = threadIdx.x >> 2;
    const int row0 = blockIdx.x * 256 + rl * 4;

    float acc[4][16];
#pragma unroll
    for (int r = 0; r < 4; r++)
#pragma unroll
        for (int j = 0; j < 16; j++) acc[r][j] = 0.0f;

    int rowc[4];
#pragma unroll
    for (int r = 0; r < 4; r++) {
        int rr = row0 + r;
        rowc[r] = rr < N ? rr : (N - 1);
    }

    if (A) macK(A, Ka, sw, rowc, cg, acc);
    if (B) macK(B, Kb, sw + offB, rowc, cg, acc);
    if (b1) addbias(b1, cg, acc);
    if (degf) {
#pragma unroll
        for (int r = 0; r < 4; r++) {
            float dg = degf[rowc[r]];
#pragma unroll
            for (int j = 0; j < 16; j++) acc[r][j] *= dg;
        }
    }
    if (D)  macK(D, Kd, sw + offD, rowc, cg, acc);
    if (E2) macK(E2, Ke, sw + offE, rowc, cg, acc);
    if (b2) addbias(b2, cg, acc);

#pragma unroll
    for (int r = 0; r < 4; r++) {
        int row = row0 + r;
        if (row < N) {
            float* cp = C + (size_t)row * 64 + cg * 16;
            *(float4*)(cp + 0)  = make_float4(acc[r][0],  acc[r][1],  acc[r][2],  acc[r][3]);
            *(float4*)(cp + 4)  = make_float4(acc[r][4],  acc[r][5],  acc[r][6],  acc[r][7]);
            *(float4*)(cp + 8)  = make_float4(acc[r][8],  acc[r][9],  acc[r][10], acc[r][11]);
            *(float4*)(cp + 12) = make_float4(acc[r][12], acc[r][13], acc[r][14], acc[r][15]);
        }
    }
}

// ---------------------------------------------------------------------------
extern "C" void kernel_launch(void* const* d_in, const int* in_sizes, int n_in,
                              void* d_out, int out_size) {
    const float* h_in = (const float*)d_in[0];
    const float* e_in = (const float*)d_in[1];
    const float* p_in = (const float*)d_in[2];
    const int*   eidx = (const int*)d_in[3];
    const float* he_W = (const float*)d_in[4];
    const float* he_b = (const float*)d_in[5];
    const float* ee_W = (const float*)d_in[6];
    const float* ee_b = (const float*)d_in[7];
    const float* pe_W = (const float*)d_in[8];
    const float* pe_b = (const float*)d_in[9];
    const float* hm_W = (const float*)d_in[10];
    const float* hm_b = (const float*)d_in[11];
    const float* hu_W = (const float*)d_in[12];
    const float* hu_b = (const float*)d_in[13];
    const float* eu_W = (const float*)d_in[14];
    const float* eu_b = (const float*)d_in[15];
    const float* pm_W = (const float*)d_in[16];
    const float* pm_b = (const float*)d_in[17];
    const float* pu_W = (const float*)d_in[18];
    const float* pu_b = (const float*)d_in[19];

    const int N = in_sizes[0] / 128;
    const int E = in_sizes[3] / 2;
    const int* send = eidx;
    const int* rec  = eidx + E;
    float* out = (float*)d_out;

    static bool attr_set = false;
    if (!attr_set) {
        cudaFuncSetAttribute(gemm_fused, cudaFuncAttributeMaxDynamicSharedMemorySize, 65536);
        attr_set = true;
    }

    float *hA, *hB, *pA, *pB, *EsA, *EsB, *S, *eraw, *deg, *Wh, *Vp, *bmh, *bmp;
    int *degi, *incl, *bsum, *rowstart, *cursor, *cols;
    cudaGetSymbolAddress((void**)&hA,  g_hA);
    cudaGetSymbolAddress((void**)&hB,  g_hB);
    cudaGetSymbolAddress((void**)&pA,  g_pA);
    cudaGetSymbolAddress((void**)&pB,  g_pB);
    cudaGetSymbolAddress((void**)&EsA, g_EsA);
    cudaGetSymbolAddress((void**)&EsB, g_EsB);
    cudaGetSymbolAddress((void**)&S,   g_S);
    cudaGetSymbolAddress((void**)&eraw, g_eraw);
    cudaGetSymbolAddress((void**)&deg, g_deg);
    cudaGetSymbolAddress((void**)&degi, g_degi);
    cudaGetSymbolAddress((void**)&incl, g_incl);
    cudaGetSymbolAddress((void**)&bsum, g_bsum);
    cudaGetSymbolAddress((void**)&rowstart, g_rowstart);
    cudaGetSymbolAddress((void**)&cursor, g_cursor);
    cudaGetSymbolAddress((void**)&cols, g_cols);
    cudaGetSymbolAddress((void**)&Wh,  g_Wh);
    cudaGetSymbolAddress((void**)&Vp,  g_Vp);
    cudaGetSymbolAddress((void**)&bmh, g_bmh);
    cudaGetSymbolAddress((void**)&bmp, g_bmp);

    const int GB = (N + 255) / 256;
    const int NB_SCAN = (N + SCAN_BLK - 1) / SCAN_BLK;
    const int GATHER_GRID = 1184;   // 8 blocks/SM, 64 warps/SM
    const float* Z = nullptr;

    // launches 0-3
    zero_i<<<(N + 255) / 256, 256>>>(degi, N);
    zero_f<<<(N * 16 + 255) / 256, 256>>>(eraw, N * 16);
    hist_i<<<(E + 255) / 256, 256>>>(rec, degi, E);
    e_scatter<<<(E * 4 + 255) / 256, 256>>>(e_in, rec, eraw, E);
    // launch 4: p embedding (K=16); launch 5 (ncu -s 5 target): h embedding K=128
    gemm_fused<<<GB, 256, 16 * 256>>>(p_in, pe_W, 16, Z, Z, 0, pe_b, Z,
                                      Z, Z, 0, Z, Z, 0, Z, pA, N);
    gemm_fused<<<GB, 256, 128 * 256>>>(h_in, he_W, 128, Z, Z, 0, he_b, Z,
                                       Z, Z, 0, Z, Z, 0, Z, hA, N);
    // CSR build
    scan1<<<NB_SCAN, SCAN_BLK>>>(degi, incl, bsum, N);
    scan2<<<1, 32>>>(bsum, NB_SCAN);
    scan3<<<(N + 255) / 256, 256>>>(degi, incl, bsum, rowstart, deg, N, E);
    copy_i<<<(N + 255) / 256, 256>>>(rowstart, cursor, N);
    csr_fill<<<(E + 255) / 256, 256>>>(send, rec, cursor, cols, E);
    // Esum0 = deg*ee_b + eraw@ee_W
    gemm_fused<<<GB, 256, 16 * 256>>>(Z, Z, 0, Z, Z, 0, ee_b, deg,
                                      eraw, ee_W, 16, Z, Z, 0, Z, EsA, N);

    for (int l = 0; l < 4; l++) {
        const float* hmW_l = hm_W + (size_t)l * 320 * 64;
        const float* bhm   = hm_b + (size_t)l * 64;
        const float* HuA   = hu_W + (size_t)l * 128 * 64;
        const float* HuB   = HuA + 64 * 64;
        const float* bhu   = hu_b + (size_t)l * 64;
        const float* U1    = eu_W + (size_t)l * 192 * 64;
        const float* U2    = U1 + 64 * 64;
        const float* U3    = U1 + 128 * 64;
        const float* beu   = eu_b + (size_t)l * 64;
        const float* pmW_l = pm_W + (size_t)l * 192 * 64;
        const float* bpm   = pm_b + (size_t)l * 64;
        const float* PuA   = pu_W + (size_t)l * 128 * 64;
        const float* PuB   = PuA + 64 * 64;
        const float* bpu   = pu_b + (size_t)l * 64;

        const bool last = (l == 3);
        float* hOut = last ? out : hB;
        float* pOut = last ? (out + (size_t)N * 64) : pB;

        // composites: Wh = hm_W[l]@HuB, bmh = bhm@HuB, Vp = pm_W[l]@PuB, bmp = bpm@PuB
        gemm_fused<<<2, 256, 64 * 256>>>(hmW_l, HuB, 64, Z, Z, 0, Z, Z,
                                         Z, Z, 0, Z, Z, 0, Z, Wh, 320);
        gemm_fused<<<1, 256, 64 * 256>>>(bhm, HuB, 64, Z, Z, 0, Z, Z,
                                         Z, Z, 0, Z, Z, 0, Z, bmh, 1);
        gemm_fused<<<1, 256, 64 * 256>>>(pmW_l, PuB, 64, Z, Z, 0, Z, Z,
                                         Z, Z, 0, Z, Z, 0, Z, Vp, 192);
        gemm_fused<<<1, 256, 64 * 256>>>(bpm, PuB, 64, Z, Z, 0, Z, Z,
                                         Z, Z, 0, Z, Z, 0, Z, bmp, 1);

        const float* W1h = Wh;                 // W_hsend @ HuB
        const float* W2h = Wh + 4096;          // W_psend @ HuB
        const float* W3h = Wh + 2 * 4096;      // W_hrec  @ HuB
        const float* W4h = Wh + 3 * 4096;      // W_prec  @ HuB
        const float* W5h = Wh + 4 * 4096;      // W_e     @ HuB
        const float* V1p = Vp;                 // V_send @ PuB
        const float* V2p = Vp + 4096;          // V_rec  @ PuB
        const float* V3p = Vp + 2 * 4096;      // V_e    @ PuB

        // S = h@W1h + p@W2h
        gemm_fused<<<GB, 256, 128 * 256>>>(hA, W1h, 64, pA, W2h, 64, Z, Z,
                                           Z, Z, 0, Z, Z, 0, Z, S, N);
        // h' = deg.*(h@W3h + p@W4h + bmh) + Esum@W5h + h@HuA + bhu
        gemm_fused<<<GB, 256, 256 * 256>>>(hA, W3h, 64, pA, W4h, 64, bmh, deg,
                                           EsA, W5h, 64, hA, HuA, 64, bhu, hOut, N);
        // h' += Adj(S)
        gather_add<<<GATHER_GRID, 256>>>(S, hOut, rowstart, cols, N);
        // T1 = h'@U1
        gemm_fused<<<GB, 256, 64 * 256>>>(hOut, U1, 64, Z, Z, 0, Z, Z,
                                          Z, Z, 0, Z, Z, 0, Z, S, N);
        // Esum' = deg.*(h'@U2 + beu) + Esum@U3
        gemm_fused<<<GB, 256, 128 * 256>>>(hOut, U2, 64, Z, Z, 0, beu, deg,
                                           EsA, U3, 64, Z, Z, 0, Z, EsB, N);
        // Esum' += Adj(T1)
        gather_add<<<GATHER_GRID, 256>>>(S, EsB, rowstart, cols, N);
        // P1 = p@V1p
        gemm_fused<<<GB, 256, 64 * 256>>>(pA, V1p, 64, Z, Z, 0, Z, Z,
                                          Z, Z, 0, Z, Z, 0, Z, S, N);
        // p' = deg.*(p@V2p + bmp) + Esum'@V3p + p@PuA + bpu
        gemm_fused<<<GB, 256, 192 * 256>>>(pA, V2p, 64, Z, Z, 0, bmp, deg,
                                           EsB, V3p, 64, pA, PuA, 64, bpu, pOut, N);
        // p' += Adj(P1)
        gather_add<<<GATHER_GRID, 256>>>(S, pOut, rowstart, cols, N);

        float* t;
        t = hA; hA = hOut; hB = t;
        t = pA; pA = pOut; pB = t;
        t = EsA; EsA = EsB; EsB = t;
    }
}